// round 12
// baseline (speedup 1.0000x reference)
#include <cuda_runtime.h>

// HierarchicalMultilabelClassificationLoss — FINAL (frozen champion, R11).
//
// Algebraic core: class_levels is deterministic (diag=1, same-16-block=w_mid,
// same-256-block=w_top, else 0, with 1 > w_mid > w_top > 0), so the
// [32,2048,2048] masked-max soft target collapses to a 3-level block-OR —
// O(N*C) instead of O(N*C^2), 0.5 MB of traffic instead of 512 MB. Weights
// are READ from the class_levels buffer (row 0: [1]=w_mid, [16]=w_top) so
// they track the actual input data.
//
// Layout (winner of R1-R10 sweep): 128 CTAs x 64 threads; warp = (batch row,
// 256-class top sector); lane = 8 contiguous classes (2x float4), so a
// 16-class mid sector is a lane pair. ONE ballot yields both hierarchy ORs:
//   top-OR = ballot != 0,   mid-OR = ballot & lane-pair mask.
// No smem, no __syncthreads anywhere.
//
// Softplus (R11): sum_e log(1+e^-|x_e|) = log(prod_e(1+e^-|x_e|)); factors
// in (1,2], product <= 256, abs err ~5e-7 — 9 MUFU instrs/lane instead of 16.
//
// Tail (R5, the one measurable win, -1.1us): per-warp partial -> fixed point
// (2^22), ONE atomicAdd on packed u64: bits[0:48)=sum, bits[48:)=warp ticket.
// The returned pre-value tells the last warp it is last AND yields the exact
// total (ret+mine) in the same round trip — no fence, no second atomic, no
// re-read. Winner writes the mean; resets state for deterministic graph replay.

#define BATCH   32
#define C       2048
#define NWARPS  256                       // 32 rows x 8 sectors
#define TPB     64                        // 2 warps per CTA
#define NBLK    (NWARPS / (TPB / 32))     // 128
#define FP_SCALE 4194304.0f               // 2^22
#define SUM_MASK ((1ULL << 48) - 1ULL)
#define TICKET_ONE (1ULL << 48)

__device__ unsigned long long g_pack = 0ULL;

__global__ __launch_bounds__(TPB)
void hml_fused_kernel(const float* __restrict__ input,
                      const float* __restrict__ target,
                      const float* __restrict__ class_levels,
                      float* __restrict__ out)
{
    const int w = blockIdx.x * (TPB / 32) + (threadIdx.x >> 5); // warp 0..255
    const int l = threadIdx.x & 31;                             // lane
    const int n = w >> 3;                 // batch row
    const int s = w & 7;                  // top sector
    const size_t base = (size_t)n * C + (s << 8) + (l << 3);

    // 4 independent 16B loads + 2 uniform scalar loads, all issued up front.
    const float4 x0 = *(const float4*)(input  + base);
    const float4 x1 = *(const float4*)(input  + base + 4);
    const float4 t0 = *(const float4*)(target + base);
    const float4 t1 = *(const float4*)(target + base + 4);
    const float w_mid = class_levels[1];   // uniform address: broadcast
    const float w_top = class_levels[16];

    const float x[8]  = {x0.x, x0.y, x0.z, x0.w, x1.x, x1.y, x1.z, x1.w};
    const float tg[8] = {t0.x, t0.y, t0.z, t0.w, t1.x, t1.y, t1.z, t1.w};

    int pos[8];
    int any = 0;
    #pragma unroll
    for (int e = 0; e < 8; e++) { pos[e] = (tg[e] > 0.5f); any |= pos[e]; }

    // One ballot -> both hierarchy levels (lane's 8 classes = half a mid sector).
    const unsigned bal = __ballot_sync(0xffffffffu, any);
    const int mid_any  = (bal & (3u << (l & 30))) != 0u;
    const int top_any  = (bal != 0u);
    const float st_neg = mid_any ? w_mid : (top_any ? w_top : 0.0f);

    // Stable BCEWithLogits; softplus accumulated as a product, one log at end.
    float acc = 0.0f, prod = 1.0f;
    #pragma unroll
    for (int e = 0; e < 8; e++) {
        const float xe = x[e];
        const float st = pos[e] ? 1.0f : st_neg;
        acc  += fmaxf(xe, 0.0f) - xe * st;
        prod *= 1.0f + __expf(-fabsf(xe));
    }
    acc += __logf(prod);

    // Warp shuffle reduce, then ONE packed atomic for this warp.
    #pragma unroll
    for (int o = 16; o > 0; o >>= 1)
        acc += __shfl_xor_sync(0xffffffffu, acc, o);

    if (l == 0) {
        const unsigned long long mine =
            (unsigned long long)__float2ull_rn(acc * FP_SCALE) + TICKET_ONE;
        const unsigned long long ret = atomicAdd(&g_pack, mine);
        if ((ret >> 48) == (unsigned long long)(NWARPS - 1)) {
            const unsigned long long total_fx = (ret + mine) & SUM_MASK;
            out[0] = (float)((double)total_fx *
                             (1.0 / (double)FP_SCALE / (double)(BATCH * C)));
            g_pack = 0ULL;                // reset for next graph replay
        }
    }
}

extern "C" void kernel_launch(void* const* d_in, const int* in_sizes, int n_in,
                              void* d_out, int out_size)
{
    const float* input        = (const float*)d_in[0];
    const float* target       = (const float*)d_in[1];
    const float* class_levels = (const float*)d_in[2];
    float* out = (float*)d_out;

    hml_fused_kernel<<<NBLK, TPB>>>(input, target, class_levels, out);
}

// round 13
// speedup vs baseline: 1.0469x; 1.0469x over previous
#include <cuda_runtime.h>

// HierarchicalMultilabelClassificationLoss — FINAL (frozen champion, R11).
//
// Algebraic core: class_levels is deterministic (diag=1, same-16-block=w_mid,
// same-256-block=w_top, else 0, with 1 > w_mid > w_top > 0), so the
// [32,2048,2048] masked-max soft target collapses to a 3-level block-OR —
// O(N*C) instead of O(N*C^2), 0.5 MB of traffic instead of 512 MB. Weights
// are READ from the class_levels buffer (row 0: [1]=w_mid, [16]=w_top) so
// they track the actual input data.
//
// Layout (winner of R1-R12 sweep): 128 CTAs x 64 threads; warp = (batch row,
// 256-class top sector); lane = 8 contiguous classes (2x float4), so a
// 16-class mid sector is a lane pair. ONE ballot yields both hierarchy ORs:
//   top-OR = ballot != 0,   mid-OR = ballot & lane-pair mask.
// No smem, no __syncthreads anywhere.
//
// Softplus (R11): sum_e log(1+e^-|x_e|) = log(prod_e(1+e^-|x_e|)); factors
// in (1,2], product <= 256, abs err ~5e-7 — 9 MUFU instrs/lane instead of 16.
//
// Tail (R5, the one measurable micro-win, -1.1us): per-warp partial -> fixed
// point (2^22), ONE atomicAdd on packed u64: bits[0:48)=sum, bits[48:)=warp
// ticket. The returned pre-value tells the last warp it is last AND yields
// the exact total (ret+mine) in the same round trip — no fence, no second
// atomic, no re-read. Winner writes the mean; resets state for graph replay.
//
// Measured floor: ncu ~5.0us with every pipe <=1.5% and DRAM = input
// footprint — grid launch/ramp + one memory round trip; body is invisible.

#define BATCH   32
#define C       2048
#define NWARPS  256                       // 32 rows x 8 sectors
#define TPB     64                        // 2 warps per CTA
#define NBLK    (NWARPS / (TPB / 32))     // 128
#define FP_SCALE 4194304.0f               // 2^22
#define SUM_MASK ((1ULL << 48) - 1ULL)
#define TICKET_ONE (1ULL << 48)

__device__ unsigned long long g_pack = 0ULL;

__global__ __launch_bounds__(TPB)
void hml_fused_kernel(const float* __restrict__ input,
                      const float* __restrict__ target,
                      const float* __restrict__ class_levels,
                      float* __restrict__ out)
{
    const int w = blockIdx.x * (TPB / 32) + (threadIdx.x >> 5); // warp 0..255
    const int l = threadIdx.x & 31;                             // lane
    const int n = w >> 3;                 // batch row
    const int s = w & 7;                  // top sector
    const size_t base = (size_t)n * C + (s << 8) + (l << 3);

    // 4 independent 16B loads + 2 uniform scalar loads, all issued up front.
    const float4 x0 = *(const float4*)(input  + base);
    const float4 x1 = *(const float4*)(input  + base + 4);
    const float4 t0 = *(const float4*)(target + base);
    const float4 t1 = *(const float4*)(target + base + 4);
    const float w_mid = class_levels[1];   // uniform address: broadcast
    const float w_top = class_levels[16];

    const float x[8]  = {x0.x, x0.y, x0.z, x0.w, x1.x, x1.y, x1.z, x1.w};
    const float tg[8] = {t0.x, t0.y, t0.z, t0.w, t1.x, t1.y, t1.z, t1.w};

    int pos[8];
    int any = 0;
    #pragma unroll
    for (int e = 0; e < 8; e++) { pos[e] = (tg[e] > 0.5f); any |= pos[e]; }

    // One ballot -> both hierarchy levels (lane's 8 classes = half a mid sector).
    const unsigned bal = __ballot_sync(0xffffffffu, any);
    const int mid_any  = (bal & (3u << (l & 30))) != 0u;
    const int top_any  = (bal != 0u);
    const float st_neg = mid_any ? w_mid : (top_any ? w_top : 0.0f);

    // Stable BCEWithLogits; softplus accumulated as a product, one log at end.
    float acc = 0.0f, prod = 1.0f;
    #pragma unroll
    for (int e = 0; e < 8; e++) {
        const float xe = x[e];
        const float st = pos[e] ? 1.0f : st_neg;
        acc  += fmaxf(xe, 0.0f) - xe * st;
        prod *= 1.0f + __expf(-fabsf(xe));
    }
    acc += __logf(prod);

    // Warp shuffle reduce, then ONE packed atomic for this warp.
    #pragma unroll
    for (int o = 16; o > 0; o >>= 1)
        acc += __shfl_xor_sync(0xffffffffu, acc, o);

    if (l == 0) {
        const unsigned long long mine =
            (unsigned long long)__float2ull_rn(acc * FP_SCALE) + TICKET_ONE;
        const unsigned long long ret = atomicAdd(&g_pack, mine);
        if ((ret >> 48) == (unsigned long long)(NWARPS - 1)) {
            const unsigned long long total_fx = (ret + mine) & SUM_MASK;
            out[0] = (float)((double)total_fx *
                             (1.0 / (double)FP_SCALE / (double)(BATCH * C)));
            g_pack = 0ULL;                // reset for next graph replay
        }
    }
}

extern "C" void kernel_launch(void* const* d_in, const int* in_sizes, int n_in,
                              void* d_out, int out_size)
{
    const float* input        = (const float*)d_in[0];
    const float* target       = (const float*)d_in[1];
    const float* class_levels = (const float*)d_in[2];
    float* out = (float*)d_out;

    hml_fused_kernel<<<NBLK, TPB>>>(input, target, class_levels, out);
}